// round 9
// baseline (speedup 1.0000x reference)
#include <cuda_runtime.h>

// Problem constants
#define B        8
#define IN_CH    64
#define OUT_CH   64
#define GROUPS   8
#define FPG      8
#define H        256
#define W        256
#define PLANE    (H * W)
#define REP_DIM  32

#define TILE     64
#define SSTRIDE  72      // padded smem row stride (float4-friendly)
#define SINT     4       // interior column base in S (left halo at col 3)
#define THREADS  256

// ---------------------------------------------------------------------------
// Single fused kernel, two independent half-tile pipelines per CTA:
//   warps 0-3: load S rows [0,34), bar.sync 1, compute out rows [0,32)
//   warps 4-7: load S rows [32,66), bar.sync 2, compute out rows [32,64)
// S rows 32/33 are written by both halves with identical values (benign).
// grid: (16 tiles, GROUPS, B), 256 threads, 64x64 tile.
// ---------------------------------------------------------------------------
__device__ __forceinline__ int reflect_idx(int i) {
    i = (i < 0) ? -i : i;
    return (i > H - 1) ? (2 * (H - 1) - i) : i;
}

__global__ __launch_bounds__(THREADS, 4)
void dyn_conv_kernel(const float* __restrict__ x,
                     const float* __restrict__ rep,
                     const float* __restrict__ Wm,
                     float* __restrict__ out) {
    const int b = blockIdx.z;
    const int g = blockIdx.y;
    const int ty = (blockIdx.x >> 2) * TILE;
    const int tx = (blockIdx.x & 3) * TILE;
    const int tid  = threadIdx.x;
    const int half = tid >> 7;        // 0: warps 0-3, 1: warps 4-7
    const int htid = tid & 127;
    const int rbase = half * 32;      // first S row this half loads

    __shared__ float S[66 * SSTRIDE];    // group-sum tile + halo
    __shared__ float k9s[FPG * 9];

    // ---- Dynamic weights: 72 dot-products (redundantly in each half) ----
    if (htid < FPG * 9) {
        const int f = (g * FPG) * 9 + htid;
        const float4* r4 = (const float4*)(rep + b * REP_DIM);
        const float4* w4 = (const float4*)(Wm + (size_t)f * REP_DIM);
        float s = 0.f;
#pragma unroll
        for (int i = 0; i < REP_DIM / 4; i++) {
            float4 rv = __ldg(&r4[i]);
            float4 wv = __ldg(&w4[i]);
            s = fmaf(rv.x, wv.x, s);
            s = fmaf(rv.y, wv.y, s);
            s = fmaf(rv.z, wv.z, s);
            s = fmaf(rv.w, wv.w, s);
        }
        k9s[htid] = (s > 0.f) ? s : 0.1f * s;
    }

    const float* xbase = x + ((size_t)(b * IN_CH + g * FPG)) * PLANE;

    // ---- Interior: 34 rows x 16 float4 per half (544 tasks / 128 threads) ----
#pragma unroll
    for (int it = 0; it < 5; it++) {
        int i = htid + it * 128;
        if (i < 34 * 16) {
            int row = rbase + (i >> 4);
            int c4  = i & 15;
            int gy = reflect_idx(ty + row - 1);
            const float* p = xbase + gy * W + tx + c4 * 4;
            float4 s = make_float4(0.f, 0.f, 0.f, 0.f);
#pragma unroll
            for (int c = 0; c < FPG; c++) {
                float4 v = *(const float4*)(p + c * PLANE);
                s.x += v.x; s.y += v.y; s.z += v.z; s.w += v.w;
            }
            *(float4*)&S[row * SSTRIDE + SINT + c4 * 4] = s;
        }
    }

    // ---- Halo columns: 34 rows x 2 sides per half ----
    if (htid < 68) {
        int row  = rbase + (htid >> 1);
        int side = htid & 1;
        int gy = reflect_idx(ty + row - 1);
        int gx = side ? reflect_idx(tx + 64) : reflect_idx(tx - 1);
        const float* p = xbase + gy * W + gx;
        float s = 0.f;
#pragma unroll
        for (int c = 0; c < FPG; c++) s += p[c * PLANE];
        S[row * SSTRIDE + (side ? (SINT + 64) : (SINT - 1))] = s;
    }

    // ---- Half-local barrier (named, 128 threads each) ----
    asm volatile("bar.sync %0, %1;" :: "r"(half + 1), "r"(128) : "memory");

    // ---- Compute: half-thread = (xq, strip2, chq) -> 4 cols, 16 rows, 2 ch
    const int xq     = htid & 15;         // 0..15 -> cols xq*4..xq*4+3
    const int strip2 = (htid >> 4) & 1;   // 0..1  -> 16-row strip within half
    const int chq    = htid >> 5;         // 0..3  -> channels chq*2, chq*2+1
    const int lx0    = xq * 4;
    const int y0     = half * 32 + strip2 * 16;
    const int co0    = chq * 2;

    float kr[18];
#pragma unroll
    for (int c = 0; c < 2; c++)
#pragma unroll
        for (int t = 0; t < 9; t++)
            kr[c * 9 + t] = k9s[(co0 + c) * 9 + t];

    // Sliding 3-row window of 6 S values (S cols lx0+3 .. lx0+8)
    float w0[6], w1[6], w2[6];
    {
        const float* Sp = &S[y0 * SSTRIDE + lx0 + 3];
#pragma unroll
        for (int j = 0; j < 6; j++) w0[j] = Sp[j];
        Sp += SSTRIDE;
#pragma unroll
        for (int j = 0; j < 6; j++) w1[j] = Sp[j];
    }

    float* op = out + ((size_t)(b * OUT_CH + g * FPG + co0)) * PLANE
                    + (ty + y0) * W + tx + lx0;

#pragma unroll 4
    for (int y = 0; y < 16; y++) {
        const float* Sp = &S[(y0 + y + 2) * SSTRIDE + lx0 + 3];
#pragma unroll
        for (int j = 0; j < 6; j++) w2[j] = Sp[j];

#pragma unroll
        for (int c = 0; c < 2; c++) {
            const float* k = &kr[c * 9];
            float4 r;
            r.x = k[0] * w0[0]; r.y = k[0] * w0[1];
            r.z = k[0] * w0[2]; r.w = k[0] * w0[3];
            r.x = fmaf(k[1], w0[1], r.x); r.y = fmaf(k[1], w0[2], r.y);
            r.z = fmaf(k[1], w0[3], r.z); r.w = fmaf(k[1], w0[4], r.w);
            r.x = fmaf(k[2], w0[2], r.x); r.y = fmaf(k[2], w0[3], r.y);
            r.z = fmaf(k[2], w0[4], r.z); r.w = fmaf(k[2], w0[5], r.w);
            r.x = fmaf(k[3], w1[0], r.x); r.y = fmaf(k[3], w1[1], r.y);
            r.z = fmaf(k[3], w1[2], r.z); r.w = fmaf(k[3], w1[3], r.w);
            r.x = fmaf(k[4], w1[1], r.x); r.y = fmaf(k[4], w1[2], r.y);
            r.z = fmaf(k[4], w1[3], r.z); r.w = fmaf(k[4], w1[4], r.w);
            r.x = fmaf(k[5], w1[2], r.x); r.y = fmaf(k[5], w1[3], r.y);
            r.z = fmaf(k[5], w1[4], r.z); r.w = fmaf(k[5], w1[5], r.w);
            r.x = fmaf(k[6], w2[0], r.x); r.y = fmaf(k[6], w2[1], r.y);
            r.z = fmaf(k[6], w2[2], r.z); r.w = fmaf(k[6], w2[3], r.w);
            r.x = fmaf(k[7], w2[1], r.x); r.y = fmaf(k[7], w2[2], r.y);
            r.z = fmaf(k[7], w2[3], r.z); r.w = fmaf(k[7], w2[4], r.w);
            r.x = fmaf(k[8], w2[2], r.x); r.y = fmaf(k[8], w2[3], r.y);
            r.z = fmaf(k[8], w2[4], r.z); r.w = fmaf(k[8], w2[5], r.w);
            __stcs((float4*)(op + c * PLANE), r);
        }
        op += W;
#pragma unroll
        for (int j = 0; j < 6; j++) { w0[j] = w1[j]; w1[j] = w2[j]; }
    }
}

// ---------------------------------------------------------------------------
// Launch: one kernel, no scratch, no inter-kernel bubble.
// ---------------------------------------------------------------------------
extern "C" void kernel_launch(void* const* d_in, const int* in_sizes, int n_in,
                              void* d_out, int out_size) {
    const float* x   = (const float*)d_in[0];   // [8, 64, 256, 256]
    const float* rep = (const float*)d_in[1];   // [8, 32]
    const float* Wm  = (const float*)d_in[2];   // [576, 32]
    float* out = (float*)d_out;                 // [8, 64, 256, 256]

    (void)in_sizes; (void)n_in; (void)out_size;

    dim3 grid(16, GROUPS, B);
    dyn_conv_kernel<<<grid, THREADS>>>(x, rep, Wm, out);
}